// round 9
// baseline (speedup 1.0000x reference)
#include <cuda_runtime.h>
#include <math.h>

#define N      16384
#define IN_F   256
#define OUT_F  128
#define ALPHA  0.2f
#define NEGV   (-9e15f)

#define BM 64
#define BN 32

// Scratch for projected Q, K, V (8 MB each) — device globals, no allocation.
__device__ float g_Q[N * OUT_F];
__device__ float g_K[N * OUT_F];
__device__ float g_V[N * OUT_F];

// ---------------------------------------------------------------------------
// Kernel 1: QKV projection.  grid = (N/64, 3), 256 threads.
// Out[64,128] = h_tile[64,256] @ W[256,128], all fp32.
// Thread tile: 4 rows x 8 cols (16 rowgroups x 16 colgroups).
// ---------------------------------------------------------------------------
__global__ __launch_bounds__(256) void qkv_kernel(
    const float* __restrict__ h,
    const float* __restrict__ Wq,
    const float* __restrict__ Wk,
    const float* __restrict__ Wv)
{
    const float* W   = (blockIdx.y == 0) ? Wq : (blockIdx.y == 1 ? Wk : Wv);
    float*       Out = (blockIdx.y == 0) ? g_Q : (blockIdx.y == 1 ? g_K : g_V);

    __shared__ float hs[64][68];       // 64 rows x 64-k chunk, +4 pad
    __shared__ float ws[64][OUT_F];    // 64 k x 128 cols

    const int tid  = threadIdx.x;
    const int ri   = tid >> 4;         // 0..15 -> rows 4*ri..4*ri+3
    const int ci   = tid & 15;         // 0..15 -> cols 8*ci..8*ci+7
    const int row0 = blockIdx.x * 64;

    float acc[4][8];
#pragma unroll
    for (int a = 0; a < 4; a++)
#pragma unroll
        for (int b = 0; b < 8; b++) acc[a][b] = 0.f;

    for (int kc = 0; kc < IN_F; kc += 64) {
        // hs: 64x64 = 1024 float4, 4 per thread
#pragma unroll
        for (int l = 0; l < 4; l++) {
            int idx = tid + l * 256;
            int r = idx >> 4, c4 = (idx & 15) * 4;
            float4 v = *(const float4*)&h[(row0 + r) * IN_F + kc + c4];
            *(float4*)&hs[r][c4] = v;
        }
        // ws: 64x128 = 2048 float4, 8 per thread
#pragma unroll
        for (int l = 0; l < 8; l++) {
            int idx = tid + l * 256;
            int r = idx >> 5, c4 = (idx & 31) * 4;
            float4 v = *(const float4*)&W[(kc + r) * OUT_F + c4];
            *(float4*)&ws[r][c4] = v;
        }
        __syncthreads();

#pragma unroll 8
        for (int k = 0; k < 64; k++) {
            float a0 = hs[ri * 4 + 0][k];
            float a1 = hs[ri * 4 + 1][k];
            float a2 = hs[ri * 4 + 2][k];
            float a3 = hs[ri * 4 + 3][k];
            float4 b0 = *(const float4*)&ws[k][ci * 8];
            float4 b1 = *(const float4*)&ws[k][ci * 8 + 4];
            float bb[8] = {b0.x, b0.y, b0.z, b0.w, b1.x, b1.y, b1.z, b1.w};
#pragma unroll
            for (int j = 0; j < 8; j++) {
                acc[0][j] = fmaf(a0, bb[j], acc[0][j]);
                acc[1][j] = fmaf(a1, bb[j], acc[1][j]);
                acc[2][j] = fmaf(a2, bb[j], acc[2][j]);
                acc[3][j] = fmaf(a3, bb[j], acc[3][j]);
            }
        }
        __syncthreads();
    }

#pragma unroll
    for (int a = 0; a < 4; a++) {
        int r = row0 + ri * 4 + a;
        float4 v0 = {acc[a][0], acc[a][1], acc[a][2], acc[a][3]};
        float4 v1 = {acc[a][4], acc[a][5], acc[a][6], acc[a][7]};
        *(float4*)&Out[r * OUT_F + ci * 8]     = v0;
        *(float4*)&Out[r * OUT_F + ci * 8 + 4] = v1;
    }
}

// ---------------------------------------------------------------------------
// Kernel 2: fused flash-style attention + leaky-relu + adj mask + softmax
//           + attn@V + ELU.  grid = N/BM = 256 CTAs, 256 threads, 2 CTAs/SM.
//
// Stage 1 (S = Q Kt): thread (ti,tj) = (tid>>4, tid&15) owns rows 4ti..4ti+3,
//                     cols 2tj..2tj+1 of the 64x32 S tile.
// Stage 2 (O += P V): thread (ri,ci) = (tid>>4, tid&15) owns rows 4ri..4ri+3,
//                     dims 8ci..8ci+7.  SAME row ownership as stage 1, so
//                     the online-softmax stats (m, l, rescale) never leave
//                     registers; only P goes through smem.
// ---------------------------------------------------------------------------
struct AttnSmem {
    float Qs[BM][128];   // 32 KB
    float Ks[BN][132];   // padded: row-major reads by 16 distinct rows
    float Vs[BN][128];
    float Ps[BM][36];    // padded to 144 B rows (16B aligned, bank shift 4)
};

__global__ __launch_bounds__(256, 2) void attn_kernel(
    const int* __restrict__ adj,
    float* __restrict__ out)
{
    extern __shared__ char smem_raw[];
    AttnSmem& sm = *reinterpret_cast<AttnSmem*>(smem_raw);

    const int tid  = threadIdx.x;
    const int ti   = tid >> 4;   // row group (4 rows), both stages
    const int tj   = tid & 15;   // stage-1 col group (2 cols)
    const int ci   = tid & 15;   // stage-2 dim group (8 dims)
    const int row0 = blockIdx.x * BM;

    // Load Q tile: 64x128 = 2048 float4, 8 per thread
#pragma unroll
    for (int l = 0; l < 8; l++) {
        int idx = tid + l * 256;
        int r = idx >> 5, c4 = (idx & 31) * 4;
        *(float4*)&sm.Qs[r][c4] = *(const float4*)&g_Q[(row0 + r) * OUT_F + c4];
    }

    const float NEG_INF = __int_as_float(0xff800000);
    float m_[4], l_[4], o_[4][8];
#pragma unroll
    for (int r = 0; r < 4; r++) {
        m_[r] = NEG_INF; l_[r] = 0.f;
#pragma unroll
        for (int d = 0; d < 8; d++) o_[r][d] = 0.f;
    }

    for (int it = 0; it < N / BN; ++it) {
        __syncthreads();   // previous stage-2 done with Vs/Ps

        // Load K,V blocks: 32x128 = 1024 float4 each, 4 per thread each
        const int cb = it * BN;
#pragma unroll
        for (int l = 0; l < 4; l++) {
            int idx = tid + l * 256;
            int r = idx >> 5, c4 = (idx & 31) * 4;
            *(float4*)&sm.Ks[r][c4] = *(const float4*)&g_K[(cb + r) * OUT_F + c4];
            *(float4*)&sm.Vs[r][c4] = *(const float4*)&g_V[(cb + r) * OUT_F + c4];
        }
        __syncthreads();

        // ---- Stage 1: S tile (4 rows x 2 cols per thread) ----
        float s[4][2];
#pragma unroll
        for (int r = 0; r < 4; r++) { s[r][0] = 0.f; s[r][1] = 0.f; }

#pragma unroll 8
        for (int k = 0; k < 128; k += 4) {
            float4 q0 = *(const float4*)&sm.Qs[ti * 4 + 0][k];
            float4 q1 = *(const float4*)&sm.Qs[ti * 4 + 1][k];
            float4 q2 = *(const float4*)&sm.Qs[ti * 4 + 2][k];
            float4 q3 = *(const float4*)&sm.Qs[ti * 4 + 3][k];
            float4 ka = *(const float4*)&sm.Ks[tj * 2 + 0][k];
            float4 kb = *(const float4*)&sm.Ks[tj * 2 + 1][k];
#define DOT4(acc, q, kv) \
            acc = fmaf(q.x, kv.x, acc); acc = fmaf(q.y, kv.y, acc); \
            acc = fmaf(q.z, kv.z, acc); acc = fmaf(q.w, kv.w, acc);
            DOT4(s[0][0], q0, ka) DOT4(s[0][1], q0, kb)
            DOT4(s[1][0], q1, ka) DOT4(s[1][1], q1, kb)
            DOT4(s[2][0], q2, ka) DOT4(s[2][1], q2, kb)
            DOT4(s[3][0], q3, ka) DOT4(s[3][1], q3, kb)
#undef DOT4
        }

        // ---- leaky-relu + adjacency mask ----
        const int gc = cb + tj * 2;
#pragma unroll
        for (int r = 0; r < 4; r++) {
            int2 av = *(const int2*)&adj[(row0 + ti * 4 + r) * N + gc];
            float s0 = s[r][0], s1 = s[r][1];
            s0 = fmaxf(s0, ALPHA * s0);           // leaky relu (works both signs)
            s1 = fmaxf(s1, ALPHA * s1);
            s[r][0] = av.x ? s0 : NEGV;
            s[r][1] = av.y ? s1 : NEGV;
        }

        // ---- online softmax update (reduce across 16 tj lanes) ----
        float scale_[4];
#pragma unroll
        for (int r = 0; r < 4; r++) {
            float mt = fmaxf(s[r][0], s[r][1]);
            mt = fmaxf(mt, __shfl_xor_sync(0xffffffffu, mt, 1));
            mt = fmaxf(mt, __shfl_xor_sync(0xffffffffu, mt, 2));
            mt = fmaxf(mt, __shfl_xor_sync(0xffffffffu, mt, 4));
            mt = fmaxf(mt, __shfl_xor_sync(0xffffffffu, mt, 8));
            float mn = fmaxf(m_[r], mt);
            float fs = __expf(m_[r] - mn);        // -inf first iter -> 0
            float p0 = __expf(s[r][0] - mn);
            float p1 = __expf(s[r][1] - mn);
            float rs = p0 + p1;
            rs += __shfl_xor_sync(0xffffffffu, rs, 1);
            rs += __shfl_xor_sync(0xffffffffu, rs, 2);
            rs += __shfl_xor_sync(0xffffffffu, rs, 4);
            rs += __shfl_xor_sync(0xffffffffu, rs, 8);
            l_[r] = l_[r] * fs + rs;
            m_[r] = mn;
            scale_[r] = fs;
            sm.Ps[ti * 4 + r][tj * 2 + 0] = p0;
            sm.Ps[ti * 4 + r][tj * 2 + 1] = p1;
        }
        __syncthreads();

        // ---- Stage 2: O = O*fs + P@V (4 rows x 8 dims per thread) ----
#pragma unroll
        for (int r = 0; r < 4; r++)
#pragma unroll
            for (int d = 0; d < 8; d++) o_[r][d] *= scale_[r];

#pragma unroll
        for (int c = 0; c < BN; c += 4) {
            float4 P0 = *(const float4*)&sm.Ps[ti * 4 + 0][c];
            float4 P1 = *(const float4*)&sm.Ps[ti * 4 + 1][c];
            float4 P2 = *(const float4*)&sm.Ps[ti * 4 + 2][c];
            float4 P3 = *(const float4*)&sm.Ps[ti * 4 + 3][c];
            float pr[4][4] = {{P0.x, P0.y, P0.z, P0.w},
                              {P1.x, P1.y, P1.z, P1.w},
                              {P2.x, P2.y, P2.z, P2.w},
                              {P3.x, P3.y, P3.z, P3.w}};
#pragma unroll
            for (int cc = 0; cc < 4; cc++) {
                float4 va = *(const float4*)&sm.Vs[c + cc][ci * 8];
                float4 vb = *(const float4*)&sm.Vs[c + cc][ci * 8 + 4];
                float vv[8] = {va.x, va.y, va.z, va.w, vb.x, vb.y, vb.z, vb.w};
#pragma unroll
                for (int r = 0; r < 4; r++)
#pragma unroll
                    for (int d = 0; d < 8; d++)
                        o_[r][d] = fmaf(pr[r][cc], vv[d], o_[r][d]);
            }
        }
    }

    // ---- epilogue: normalize, ELU, store ----
#pragma unroll
    for (int r = 0; r < 4; r++) {
        float inv = 1.f / l_[r];
        int row = row0 + ti * 4 + r;
        float v[8];
#pragma unroll
        for (int d = 0; d < 8; d++) {
            float x = o_[r][d] * inv;
            v[d] = (x > 0.f) ? x : (__expf(x) - 1.f);
        }
        float4 v0 = {v[0], v[1], v[2], v[3]};
        float4 v1 = {v[4], v[5], v[6], v[7]};
        *(float4*)&out[row * OUT_F + ci * 8]     = v0;
        *(float4*)&out[row * OUT_F + ci * 8 + 4] = v1;
    }
}

// ---------------------------------------------------------------------------
extern "C" void kernel_launch(void* const* d_in, const int* in_sizes, int n_in,
                              void* d_out, int out_size)
{
    const float* h   = (const float*)d_in[0];
    const int*   adj = (const int*)  d_in[1];
    const float* Wq  = (const float*)d_in[2];
    const float* Wk  = (const float*)d_in[3];
    const float* Wv  = (const float*)d_in[4];
    float*       out = (float*)d_out;

    (void)in_sizes; (void)n_in; (void)out_size;

    const int smem_bytes = (int)sizeof(AttnSmem);
    cudaFuncSetAttribute(attn_kernel,
                         cudaFuncAttributeMaxDynamicSharedMemorySize,
                         smem_bytes);

    qkv_kernel<<<dim3(N / 64, 3), 256>>>(h, Wq, Wk, Wv);
    attn_kernel<<<N / BM, 256, smem_bytes>>>(adj, out);
}

// round 10
// speedup vs baseline: 1.0015x; 1.0015x over previous
#include <cuda_runtime.h>
#include <math.h>

#define N      16384
#define IN_F   256
#define OUT_F  128
#define ALPHA  0.2f
#define NEGV   (-9e15f)

#define BM 64
#define BN 32

// Scratch for projected Q, K, V (8 MB each) — device globals, no allocation.
__device__ float g_Q[N * OUT_F];
__device__ float g_K[N * OUT_F];
__device__ float g_V[N * OUT_F];

// ---------------------------------------------------------------------------
// Kernel 1: QKV projection.  grid = (N/64, 3), 256 threads.
// Out[64,128] = h_tile[64,256] @ W[256,128], all fp32.
// Thread tile: 4 rows x 8 cols (16 rowgroups x 16 colgroups).
// ---------------------------------------------------------------------------
__global__ __launch_bounds__(256) void qkv_kernel(
    const float* __restrict__ h,
    const float* __restrict__ Wq,
    const float* __restrict__ Wk,
    const float* __restrict__ Wv)
{
    const float* W   = (blockIdx.y == 0) ? Wq : (blockIdx.y == 1 ? Wk : Wv);
    float*       Out = (blockIdx.y == 0) ? g_Q : (blockIdx.y == 1 ? g_K : g_V);

    __shared__ float hs[64][68];       // 64 rows x 64-k chunk, +4 pad
    __shared__ float ws[64][OUT_F];    // 64 k x 128 cols

    const int tid  = threadIdx.x;
    const int ri   = tid >> 4;         // 0..15 -> rows 4*ri..4*ri+3
    const int ci   = tid & 15;         // 0..15 -> cols 8*ci..8*ci+7
    const int row0 = blockIdx.x * 64;

    float acc[4][8];
#pragma unroll
    for (int a = 0; a < 4; a++)
#pragma unroll
        for (int b = 0; b < 8; b++) acc[a][b] = 0.f;

    for (int kc = 0; kc < IN_F; kc += 64) {
        // hs: 64x64 = 1024 float4, 4 per thread
#pragma unroll
        for (int l = 0; l < 4; l++) {
            int idx = tid + l * 256;
            int r = idx >> 4, c4 = (idx & 15) * 4;
            float4 v = *(const float4*)&h[(row0 + r) * IN_F + kc + c4];
            *(float4*)&hs[r][c4] = v;
        }
        // ws: 64x128 = 2048 float4, 8 per thread
#pragma unroll
        for (int l = 0; l < 8; l++) {
            int idx = tid + l * 256;
            int r = idx >> 5, c4 = (idx & 31) * 4;
            float4 v = *(const float4*)&W[(kc + r) * OUT_F + c4];
            *(float4*)&ws[r][c4] = v;
        }
        __syncthreads();

#pragma unroll 8
        for (int k = 0; k < 64; k++) {
            float a0 = hs[ri * 4 + 0][k];
            float a1 = hs[ri * 4 + 1][k];
            float a2 = hs[ri * 4 + 2][k];
            float a3 = hs[ri * 4 + 3][k];
            float4 b0 = *(const float4*)&ws[k][ci * 8];
            float4 b1 = *(const float4*)&ws[k][ci * 8 + 4];
            float bb[8] = {b0.x, b0.y, b0.z, b0.w, b1.x, b1.y, b1.z, b1.w};
#pragma unroll
            for (int j = 0; j < 8; j++) {
                acc[0][j] = fmaf(a0, bb[j], acc[0][j]);
                acc[1][j] = fmaf(a1, bb[j], acc[1][j]);
                acc[2][j] = fmaf(a2, bb[j], acc[2][j]);
                acc[3][j] = fmaf(a3, bb[j], acc[3][j]);
            }
        }
        __syncthreads();
    }

#pragma unroll
    for (int a = 0; a < 4; a++) {
        int r = row0 + ri * 4 + a;
        float4 v0 = {acc[a][0], acc[a][1], acc[a][2], acc[a][3]};
        float4 v1 = {acc[a][4], acc[a][5], acc[a][6], acc[a][7]};
        *(float4*)&Out[r * OUT_F + ci * 8]     = v0;
        *(float4*)&Out[r * OUT_F + ci * 8 + 4] = v1;
    }
}

// ---------------------------------------------------------------------------
// Kernel 2: fused flash-style attention + leaky-relu + adj mask + softmax
//           + attn@V + ELU.  grid = N/BM = 256 CTAs, 256 threads, 2 CTAs/SM.
//
// Stage 1 (S = Q Kt): thread (ti,tj) = (tid>>4, tid&15) owns rows 4ti..4ti+3,
//                     cols 2tj..2tj+1 of the 64x32 S tile.
// Stage 2 (O += P V): thread (ri,ci) = (tid>>4, tid&15) owns rows 4ri..4ri+3,
//                     dims 8ci..8ci+7.  SAME row ownership as stage 1, so
//                     the online-softmax stats (m, l, rescale) never leave
//                     registers; only P goes through smem.
// ---------------------------------------------------------------------------
struct AttnSmem {
    float Qs[BM][128];   // 32 KB
    float Ks[BN][132];   // padded: row-major reads by 16 distinct rows
    float Vs[BN][128];
    float Ps[BM][36];    // padded to 144 B rows (16B aligned, bank shift 4)
};

__global__ __launch_bounds__(256, 2) void attn_kernel(
    const int* __restrict__ adj,
    float* __restrict__ out)
{
    extern __shared__ char smem_raw[];
    AttnSmem& sm = *reinterpret_cast<AttnSmem*>(smem_raw);

    const int tid  = threadIdx.x;
    const int ti   = tid >> 4;   // row group (4 rows), both stages
    const int tj   = tid & 15;   // stage-1 col group (2 cols)
    const int ci   = tid & 15;   // stage-2 dim group (8 dims)
    const int row0 = blockIdx.x * BM;

    // Load Q tile: 64x128 = 2048 float4, 8 per thread
#pragma unroll
    for (int l = 0; l < 8; l++) {
        int idx = tid + l * 256;
        int r = idx >> 5, c4 = (idx & 31) * 4;
        *(float4*)&sm.Qs[r][c4] = *(const float4*)&g_Q[(row0 + r) * OUT_F + c4];
    }

    const float NEG_INF = __int_as_float(0xff800000);
    float m_[4], l_[4], o_[4][8];
#pragma unroll
    for (int r = 0; r < 4; r++) {
        m_[r] = NEG_INF; l_[r] = 0.f;
#pragma unroll
        for (int d = 0; d < 8; d++) o_[r][d] = 0.f;
    }

    for (int it = 0; it < N / BN; ++it) {
        __syncthreads();   // previous stage-2 done with Vs/Ps

        // Load K,V blocks: 32x128 = 1024 float4 each, 4 per thread each
        const int cb = it * BN;
#pragma unroll
        for (int l = 0; l < 4; l++) {
            int idx = tid + l * 256;
            int r = idx >> 5, c4 = (idx & 31) * 4;
            *(float4*)&sm.Ks[r][c4] = *(const float4*)&g_K[(cb + r) * OUT_F + c4];
            *(float4*)&sm.Vs[r][c4] = *(const float4*)&g_V[(cb + r) * OUT_F + c4];
        }
        __syncthreads();

        // ---- Stage 1: S tile (4 rows x 2 cols per thread) ----
        float s[4][2];
#pragma unroll
        for (int r = 0; r < 4; r++) { s[r][0] = 0.f; s[r][1] = 0.f; }

#pragma unroll 8
        for (int k = 0; k < 128; k += 4) {
            float4 q0 = *(const float4*)&sm.Qs[ti * 4 + 0][k];
            float4 q1 = *(const float4*)&sm.Qs[ti * 4 + 1][k];
            float4 q2 = *(const float4*)&sm.Qs[ti * 4 + 2][k];
            float4 q3 = *(const float4*)&sm.Qs[ti * 4 + 3][k];
            float4 ka = *(const float4*)&sm.Ks[tj * 2 + 0][k];
            float4 kb = *(const float4*)&sm.Ks[tj * 2 + 1][k];
#define DOT4(acc, q, kv) \
            acc = fmaf(q.x, kv.x, acc); acc = fmaf(q.y, kv.y, acc); \
            acc = fmaf(q.z, kv.z, acc); acc = fmaf(q.w, kv.w, acc);
            DOT4(s[0][0], q0, ka) DOT4(s[0][1], q0, kb)
            DOT4(s[1][0], q1, ka) DOT4(s[1][1], q1, kb)
            DOT4(s[2][0], q2, ka) DOT4(s[2][1], q2, kb)
            DOT4(s[3][0], q3, ka) DOT4(s[3][1], q3, kb)
#undef DOT4
        }

        // ---- leaky-relu + adjacency mask ----
        const int gc = cb + tj * 2;
#pragma unroll
        for (int r = 0; r < 4; r++) {
            int2 av = *(const int2*)&adj[(row0 + ti * 4 + r) * N + gc];
            float s0 = s[r][0], s1 = s[r][1];
            s0 = fmaxf(s0, ALPHA * s0);           // leaky relu (works both signs)
            s1 = fmaxf(s1, ALPHA * s1);
            s[r][0] = av.x ? s0 : NEGV;
            s[r][1] = av.y ? s1 : NEGV;
        }

        // ---- online softmax update (reduce across 16 tj lanes) ----
        float scale_[4];
#pragma unroll
        for (int r = 0; r < 4; r++) {
            float mt = fmaxf(s[r][0], s[r][1]);
            mt = fmaxf(mt, __shfl_xor_sync(0xffffffffu, mt, 1));
            mt = fmaxf(mt, __shfl_xor_sync(0xffffffffu, mt, 2));
            mt = fmaxf(mt, __shfl_xor_sync(0xffffffffu, mt, 4));
            mt = fmaxf(mt, __shfl_xor_sync(0xffffffffu, mt, 8));
            float mn = fmaxf(m_[r], mt);
            float fs = __expf(m_[r] - mn);        // -inf first iter -> 0
            float p0 = __expf(s[r][0] - mn);
            float p1 = __expf(s[r][1] - mn);
            float rs = p0 + p1;
            rs += __shfl_xor_sync(0xffffffffu, rs, 1);
            rs += __shfl_xor_sync(0xffffffffu, rs, 2);
            rs += __shfl_xor_sync(0xffffffffu, rs, 4);
            rs += __shfl_xor_sync(0xffffffffu, rs, 8);
            l_[r] = l_[r] * fs + rs;
            m_[r] = mn;
            scale_[r] = fs;
            sm.Ps[ti * 4 + r][tj * 2 + 0] = p0;
            sm.Ps[ti * 4 + r][tj * 2 + 1] = p1;
        }
        __syncthreads();

        // ---- Stage 2: O = O*fs + P@V (4 rows x 8 dims per thread) ----
#pragma unroll
        for (int r = 0; r < 4; r++)
#pragma unroll
            for (int d = 0; d < 8; d++) o_[r][d] *= scale_[r];

#pragma unroll
        for (int c = 0; c < BN; c += 4) {
            float4 P0 = *(const float4*)&sm.Ps[ti * 4 + 0][c];
            float4 P1 = *(const float4*)&sm.Ps[ti * 4 + 1][c];
            float4 P2 = *(const float4*)&sm.Ps[ti * 4 + 2][c];
            float4 P3 = *(const float4*)&sm.Ps[ti * 4 + 3][c];
            float pr[4][4] = {{P0.x, P0.y, P0.z, P0.w},
                              {P1.x, P1.y, P1.z, P1.w},
                              {P2.x, P2.y, P2.z, P2.w},
                              {P3.x, P3.y, P3.z, P3.w}};
#pragma unroll
            for (int cc = 0; cc < 4; cc++) {
                float4 va = *(const float4*)&sm.Vs[c + cc][ci * 8];
                float4 vb = *(const float4*)&sm.Vs[c + cc][ci * 8 + 4];
                float vv[8] = {va.x, va.y, va.z, va.w, vb.x, vb.y, vb.z, vb.w};
#pragma unroll
                for (int r = 0; r < 4; r++)
#pragma unroll
                    for (int d = 0; d < 8; d++)
                        o_[r][d] = fmaf(pr[r][cc], vv[d], o_[r][d]);
            }
        }
    }

    // ---- epilogue: normalize, ELU, store ----
#pragma unroll
    for (int r = 0; r < 4; r++) {
        float inv = 1.f / l_[r];
        int row = row0 + ti * 4 + r;
        float v[8];
#pragma unroll
        for (int d = 0; d < 8; d++) {
            float x = o_[r][d] * inv;
            v[d] = (x > 0.f) ? x : (__expf(x) - 1.f);
        }
        float4 v0 = {v[0], v[1], v[2], v[3]};
        float4 v1 = {v[4], v[5], v[6], v[7]};
        *(float4*)&out[row * OUT_F + ci * 8]     = v0;
        *(float4*)&out[row * OUT_F + ci * 8 + 4] = v1;
    }
}

// ---------------------------------------------------------------------------
extern "C" void kernel_launch(void* const* d_in, const int* in_sizes, int n_in,
                              void* d_out, int out_size)
{
    const float* h   = (const float*)d_in[0];
    const int*   adj = (const int*)  d_in[1];
    const float* Wq  = (const float*)d_in[2];
    const float* Wk  = (const float*)d_in[3];
    const float* Wv  = (const float*)d_in[4];
    float*       out = (float*)d_out;

    (void)in_sizes; (void)n_in; (void)out_size;

    const int smem_bytes = (int)sizeof(AttnSmem);
    cudaFuncSetAttribute(attn_kernel,
                         cudaFuncAttributeMaxDynamicSharedMemorySize,
                         smem_bytes);

    qkv_kernel<<<dim3(N / 64, 3), 256>>>(h, Wq, Wk, Wv);
    attn_kernel<<<N / BM, 256, smem_bytes>>>(adj, out);
}

// round 14
// speedup vs baseline: 6.2481x; 6.2388x over previous
#include <cuda_runtime.h>
#include <cuda_fp16.h>
#include <math.h>
#include <stdint.h>

#define NN     16384
#define IN_F   256
#define OUT_F  128
#define ALPHA  0.2f
#define LOG2E  1.4426950408889634f

// ---------------- device-global scratch (no allocation) --------------------
__device__ float g_Q[NN * OUT_F];
__device__ float g_K[NN * OUT_F];
__device__ float g_V[NN * OUT_F];
__device__ __half g_Qh[NN * OUT_F];
__device__ __half g_Ql[NN * OUT_F];
// K fragments: [blk 256][kk 8][j 8][lane 32] uint4 = (bh0,bh1,bl0,bl1)  (8 MB)
__device__ __align__(16) uint4 g_Kp[256 * 2048];
// V fragments: [blk 256][kk 4][dt 16][lane 32] uint2 = (b0,b1)          (4 MB)
__device__ __align__(16) uint2 g_Vp[256 * 2048];

// ---------------- helpers ----------------------------------------------
__device__ __forceinline__ uint32_t smem_u32(const void* p) {
    uint32_t a;
    asm("{ .reg .u64 t; cvta.to.shared.u64 t, %1; cvt.u32.u64 %0, t; }" : "=r"(a) : "l"(p));
    return a;
}
__device__ __forceinline__ float ex2f(float x) {
    float y; asm("ex2.approx.f32 %0, %1;" : "=f"(y) : "f"(x)); return y;
}
__device__ __forceinline__ void cpa16(uint32_t s, const void* g) {
    asm volatile("cp.async.cg.shared.global [%0], [%1], 16;" :: "r"(s), "l"(g));
}
#define CPA_COMMIT() asm volatile("cp.async.commit_group;" ::: "memory")
#define CPA_WAIT1()  asm volatile("cp.async.wait_group 1;" ::: "memory")

// m16n8k16 fp16 mma, fp32 accumulate
#define MMA4(c, a, b0v, b1v) \
    asm volatile("mma.sync.aligned.m16n8k16.row.col.f32.f16.f16.f32 " \
        "{%0,%1,%2,%3},{%4,%5,%6,%7},{%8,%9},{%0,%1,%2,%3};" \
        : "+f"((c)[0]), "+f"((c)[1]), "+f"((c)[2]), "+f"((c)[3]) \
        : "r"((a)[0]), "r"((a)[1]), "r"((a)[2]), "r"((a)[3]), "r"(b0v), "r"(b1v))

__device__ __forceinline__ uint32_t h2u(__half2 h) {
    uint32_t u; asm("mov.b32 %0, %1;" : "=r"(u) : "r"(*(uint32_t*)&h)); return u;
}
__device__ __forceinline__ void split_h(float x, __half& h, __half& l) {
    h = __float2half_rn(x);
    l = __float2half_rn(x - __half2float(h));
}

// ---------------------------------------------------------------------------
// Kernel 1: QKV projection (fp32 FFMA)
// ---------------------------------------------------------------------------
__global__ __launch_bounds__(256) void qkv_kernel(
    const float* __restrict__ h, const float* __restrict__ Wq,
    const float* __restrict__ Wk, const float* __restrict__ Wv)
{
    const float* W   = (blockIdx.y == 0) ? Wq : (blockIdx.y == 1 ? Wk : Wv);
    float*       Out = (blockIdx.y == 0) ? g_Q : (blockIdx.y == 1 ? g_K : g_V);

    __shared__ float hs[64][68];
    __shared__ float ws[64][OUT_F];

    const int tid = threadIdx.x, ri = tid >> 4, ci = tid & 15;
    const int row0 = blockIdx.x * 64;
    float acc[4][8];
#pragma unroll
    for (int a = 0; a < 4; a++)
#pragma unroll
        for (int b = 0; b < 8; b++) acc[a][b] = 0.f;

    for (int kc = 0; kc < IN_F; kc += 64) {
#pragma unroll
        for (int l = 0; l < 4; l++) {
            int idx = tid + l * 256, r = idx >> 4, c4 = (idx & 15) * 4;
            *(float4*)&hs[r][c4] = *(const float4*)&h[(row0 + r) * IN_F + kc + c4];
        }
#pragma unroll
        for (int l = 0; l < 8; l++) {
            int idx = tid + l * 256, r = idx >> 5, c4 = (idx & 31) * 4;
            *(float4*)&ws[r][c4] = *(const float4*)&W[(kc + r) * OUT_F + c4];
        }
        __syncthreads();
#pragma unroll 8
        for (int k = 0; k < 64; k++) {
            float a0 = hs[ri * 4 + 0][k], a1 = hs[ri * 4 + 1][k];
            float a2 = hs[ri * 4 + 2][k], a3 = hs[ri * 4 + 3][k];
            float4 b0 = *(const float4*)&ws[k][ci * 8];
            float4 b1 = *(const float4*)&ws[k][ci * 8 + 4];
            float bb[8] = {b0.x, b0.y, b0.z, b0.w, b1.x, b1.y, b1.z, b1.w};
#pragma unroll
            for (int j = 0; j < 8; j++) {
                acc[0][j] = fmaf(a0, bb[j], acc[0][j]);
                acc[1][j] = fmaf(a1, bb[j], acc[1][j]);
                acc[2][j] = fmaf(a2, bb[j], acc[2][j]);
                acc[3][j] = fmaf(a3, bb[j], acc[3][j]);
            }
        }
        __syncthreads();
    }
#pragma unroll
    for (int a = 0; a < 4; a++) {
        int r = row0 + ri * 4 + a;
        float4 v0 = {acc[a][0], acc[a][1], acc[a][2], acc[a][3]};
        float4 v1 = {acc[a][4], acc[a][5], acc[a][6], acc[a][7]};
        *(float4*)&Out[r * OUT_F + ci * 8]     = v0;
        *(float4*)&Out[r * OUT_F + ci * 8 + 4] = v1;
    }
}

// ---------------------------------------------------------------------------
// Kernel 2: pack Q (fp16 hi/lo rows), K (hi/lo B-fragments), V (B-fragments)
// ---------------------------------------------------------------------------
__global__ __launch_bounds__(256) void pack_kernel() {
    const int b = blockIdx.x, tid = threadIdx.x;

    // Q rows [b*64, b*64+64): elementwise split
    for (int idx = tid; idx < 64 * 128; idx += 256) {
        int r = b * 64 + (idx >> 7), c = idx & 127;
        float x = g_Q[(size_t)r * 128 + c];
        __half h, l; split_h(x, h, l);
        g_Qh[(size_t)r * 128 + c] = h;
        g_Ql[(size_t)r * 128 + c] = l;
    }
    // K fragments: B-frag for m16n8k16 row.col — b_row = k, b_col = n.
    // thread(lane) holds K[n = 8j+g][k = 16kk + 2t + {0,1}] (x) and k+8+{0,1} (y)
    for (int idx = tid; idx < 2048; idx += 256) {
        int kk = idx >> 8, j = (idx >> 5) & 7, lane = idx & 31;
        int g = lane >> 2, t = lane & 3;
        int n = b * 64 + 8 * j + g;
        int d = 16 * kk + 2 * t;
        const float* kr = &g_K[(size_t)n * 128];
        __half h0, l0, h1, l1, h2, l2, h3, l3;
        split_h(kr[d],     h0, l0); split_h(kr[d + 1], h1, l1);
        split_h(kr[d + 8], h2, l2); split_h(kr[d + 9], h3, l3);
        uint4 u;
        u.x = h2u(__halves2half2(h0, h1));
        u.y = h2u(__halves2half2(h2, h3));
        u.z = h2u(__halves2half2(l0, l1));
        u.w = h2u(__halves2half2(l2, l3));
        g_Kp[(size_t)b * 2048 + idx] = u;
    }
    // V fragments: B-frag, b_row = key k (contraction), b_col = dim.
    // thread holds V[k0+{0,1}][dim] (x) and V[k0+8+{0,1}][dim] (y)
    for (int idx = tid; idx < 2048; idx += 256) {
        int kk = idx >> 9, dt = (idx >> 5) & 15, lane = idx & 31;
        int g = lane >> 2, t = lane & 3;
        int k0 = b * 64 + 16 * kk + 2 * t;
        int dim = 8 * dt + g;
        uint2 u;
        u.x = h2u(__halves2half2(__float2half_rn(g_V[(size_t)k0 * 128 + dim]),
                                 __float2half_rn(g_V[(size_t)(k0 + 1) * 128 + dim])));
        u.y = h2u(__halves2half2(__float2half_rn(g_V[(size_t)(k0 + 8) * 128 + dim]),
                                 __float2half_rn(g_V[(size_t)(k0 + 9) * 128 + dim])));
        g_Vp[(size_t)b * 2048 + idx] = u;
    }
}

// ---------------------------------------------------------------------------
// Kernel 3: flash attention via mma.sync.  128 CTAs x 256 thr (8 warps x 16 rows).
// ---------------------------------------------------------------------------
#define SMEM_KV   49152                 // Kp 32KB + Vp 16KB
#define ADJ_ROWB  272                   // 64 ints padded to 68 (bank spread)
#define SMEM_ADJ  (128 * ADJ_ROWB)      // 34816
#define SMEM_DYN  (2 * SMEM_KV + 2 * SMEM_ADJ)

__device__ __forceinline__ void prefetch_tiles(uint32_t smb, int buf, int blk,
                                               const int* adj, int qrow0, int tid)
{
    uint32_t dk = smb + (uint32_t)buf * SMEM_KV;
    const unsigned char* srcK = (const unsigned char*)g_Kp + (size_t)blk * 32768;
    const unsigned char* srcV = (const unsigned char*)g_Vp + (size_t)blk * 16384;
#pragma unroll
    for (int i = 0; i < 8; i++) { int o = (tid + i * 256) * 16; cpa16(dk + o, srcK + o); }
#pragma unroll
    for (int i = 0; i < 4; i++) { int o = (tid + i * 256) * 16; cpa16(dk + 32768 + o, srcV + o); }
    uint32_t da = smb + 2 * SMEM_KV + (uint32_t)buf * SMEM_ADJ;
#pragma unroll
    for (int i = 0; i < 8; i++) {
        int c = tid + i * 256;                 // 2048 x 16B chunks
        int row = c >> 4, c16 = c & 15;
        const int* src = adj + (size_t)(qrow0 + row) * NN + blk * 64 + c16 * 4;
        cpa16(da + row * ADJ_ROWB + c16 * 16, src);
    }
}

__global__ __launch_bounds__(256, 1) void attn_kernel(
    const int* __restrict__ adj, float* __restrict__ out)
{
    extern __shared__ __align__(16) unsigned char smraw[];
    const int tid = threadIdx.x, w = tid >> 5, lane = tid & 31;
    const int g = lane >> 2, t = lane & 3;
    const int qrow0 = blockIdx.x * 128;
    const int r0 = qrow0 + w * 16 + g, r1 = r0 + 8;
    const uint32_t smb = smem_u32(smraw);

    prefetch_tiles(smb, 0, 0, adj, qrow0, tid); CPA_COMMIT();
    prefetch_tiles(smb, 1, 1, adj, qrow0, tid); CPA_COMMIT();

    // Q fragments (held in registers for the whole kernel)
    uint32_t qh[8][4], ql[8][4];
#pragma unroll
    for (int kk = 0; kk < 8; kk++) {
        int c = kk * 16 + 2 * t;
        qh[kk][0] = *(const uint32_t*)&g_Qh[(size_t)r0 * 128 + c];
        qh[kk][1] = *(const uint32_t*)&g_Qh[(size_t)r1 * 128 + c];
        qh[kk][2] = *(const uint32_t*)&g_Qh[(size_t)r0 * 128 + c + 8];
        qh[kk][3] = *(const uint32_t*)&g_Qh[(size_t)r1 * 128 + c + 8];
        ql[kk][0] = *(const uint32_t*)&g_Ql[(size_t)r0 * 128 + c];
        ql[kk][1] = *(const uint32_t*)&g_Ql[(size_t)r1 * 128 + c];
        ql[kk][2] = *(const uint32_t*)&g_Ql[(size_t)r0 * 128 + c + 8];
        ql[kk][3] = *(const uint32_t*)&g_Ql[(size_t)r1 * 128 + c + 8];
    }

    float o[16][4];
#pragma unroll
    for (int dt = 0; dt < 16; dt++)
#pragma unroll
        for (int i = 0; i < 4; i++) o[dt][i] = 0.f;
    float m0 = -1e30f, m1 = -1e30f, l0 = 0.f, l1 = 0.f;

    const int arow0 = (w * 16 + g) * (ADJ_ROWB / 8);       // int2 units
    const int arow1 = (w * 16 + g + 8) * (ADJ_ROWB / 8);

    for (int it = 0; it < 256; ++it) {
        CPA_WAIT1();
        __syncthreads();
        const int buf = it & 1;
        const uint4* khl = (const uint4*)(smraw + buf * SMEM_KV);
        const uint2* vbf = (const uint2*)(smraw + buf * SMEM_KV + 32768);
        const int2*  am  = (const int2*)(smraw + 2 * SMEM_KV + buf * SMEM_ADJ);

        // ---- S = Q K^T (3-term fp16 split, Kh frag reused) ----
        float s[8][4];
#pragma unroll
        for (int j = 0; j < 8; j++)
#pragma unroll
            for (int i = 0; i < 4; i++) s[j][i] = 0.f;
#pragma unroll
        for (int kk = 0; kk < 8; kk++) {
#pragma unroll
            for (int j = 0; j < 8; j++) {
                uint4 b = khl[(((kk << 3) + j) << 5) + lane];
                MMA4(s[j], qh[kk], b.x, b.y);
                MMA4(s[j], ql[kk], b.x, b.y);
                MMA4(s[j], qh[kk], b.z, b.w);
            }
        }

        // ---- leaky relu + adjacency mask + block max ----
        float bm0 = -3e38f, bm1 = -3e38f;
#pragma unroll
        for (int j = 0; j < 8; j++) {
            int2 a0 = am[arow0 + 4 * j + t];
            int2 a1 = am[arow1 + 4 * j + t];
            float v;
            v = s[j][0]; v = fmaxf(v, ALPHA * v); s[j][0] = a0.x ? v : -3e38f;
            v = s[j][1]; v = fmaxf(v, ALPHA * v); s[j][1] = a0.y ? v : -3e38f;
            v = s[j][2]; v = fmaxf(v, ALPHA * v); s[j][2] = a1.x ? v : -3e38f;
            v = s[j][3]; v = fmaxf(v, ALPHA * v); s[j][3] = a1.y ? v : -3e38f;
            bm0 = fmaxf(bm0, fmaxf(s[j][0], s[j][1]));
            bm1 = fmaxf(bm1, fmaxf(s[j][2], s[j][3]));
        }
        bm0 = fmaxf(bm0, __shfl_xor_sync(0xffffffffu, bm0, 1));
        bm0 = fmaxf(bm0, __shfl_xor_sync(0xffffffffu, bm0, 2));
        bm1 = fmaxf(bm1, __shfl_xor_sync(0xffffffffu, bm1, 1));
        bm1 = fmaxf(bm1, __shfl_xor_sync(0xffffffffu, bm1, 2));
        float nm0 = fmaxf(m0, bm0), nm1 = fmaxf(m1, bm1);
        float fs0 = ex2f((m0 - nm0) * LOG2E);
        float fs1 = ex2f((m1 - nm1) * LOG2E);
        m0 = nm0; m1 = nm1;
        const float n0s = nm0 * LOG2E, n1s = nm1 * LOG2E;

        // ---- exp + convert to fp16 PV A-fragments (register-to-register) ----
        // S C-frag (m16n8): s[j][0,1] = row g, cols 2t,2t+1 of tile j; s[j][2,3] = row g+8.
        // PV A-frag (m16k16): a[0]=row g,k=2t; a[1]=row g+8,k=2t; a[2]=row g,k=2t+8; a[3]=row g+8,k=2t+8.
        // Tile j = 2kk+half supplies k-halves of PV A-frag kk: half0 -> a[0],a[1]; half1 -> a[2],a[3].
        uint32_t pf[4][4];
        float ps0 = 0.f, ps1 = 0.f;
#pragma unroll
        for (int kk = 0; kk < 4; kk++) {
#pragma unroll
            for (int half = 0; half < 2; half++) {
                int j = 2 * kk + half;
                float p0 = ex2f(fmaf(s[j][0], LOG2E, -n0s));
                float p1 = ex2f(fmaf(s[j][1], LOG2E, -n0s));
                float p2 = ex2f(fmaf(s[j][2], LOG2E, -n1s));
                float p3 = ex2f(fmaf(s[j][3], LOG2E, -n1s));
                __half2 hA = __floats2half2_rn(p0, p1);
                __half2 hB = __floats2half2_rn(p2, p3);
                pf[kk][0 + 2 * half] = h2u(hA);
                pf[kk][1 + 2 * half] = h2u(hB);
                float2 fA = __half22float2(hA), fB = __half22float2(hB);
                ps0 += fA.x + fA.y;
                ps1 += fB.x + fB.y;
            }
        }
        l0 = l0 * fs0 + ps0;
        l1 = l1 * fs1 + ps1;

        // ---- rescale O, then O += P V ----
#pragma unroll
        for (int dt = 0; dt < 16; dt++) {
            o[dt][0] *= fs0; o[dt][1] *= fs0;
            o[dt][2] *= fs1; o[dt][3] *= fs1;
        }
#pragma unroll
        for (int kk = 0; kk < 4; kk++) {
#pragma unroll
            for (int dt = 0; dt < 16; dt++) {
                uint2 v = vbf[(((kk << 4) + dt) << 5) + lane];
                MMA4(o[dt], pf[kk], v.x, v.y);
            }
        }

        __syncthreads();
        if (it + 2 < 256)
            prefetch_tiles(smb, buf, it + 2, adj, qrow0, tid);
        CPA_COMMIT();
    }

    // ---- epilogue: reduce l across quad, normalize, ELU, store ----
    l0 += __shfl_xor_sync(0xffffffffu, l0, 1);
    l0 += __shfl_xor_sync(0xffffffffu, l0, 2);
    l1 += __shfl_xor_sync(0xffffffffu, l1, 1);
    l1 += __shfl_xor_sync(0xffffffffu, l1, 2);
    const float i0 = 1.f / l0, i1 = 1.f / l1;
#pragma unroll
    for (int dt = 0; dt < 16; dt++) {
        float x0 = o[dt][0] * i0, x1 = o[dt][1] * i0;
        float x2 = o[dt][2] * i1, x3 = o[dt][3] * i1;
        x0 = (x0 > 0.f) ? x0 : (__expf(x0) - 1.f);
        x1 = (x1 > 0.f) ? x1 : (__expf(x1) - 1.f);
        x2 = (x2 > 0.f) ? x2 : (__expf(x2) - 1.f);
        x3 = (x3 > 0.f) ? x3 : (__expf(x3) - 1.f);
        int c = 8 * dt + 2 * t;
        *(float2*)&out[(size_t)r0 * 128 + c] = make_float2(x0, x1);
        *(float2*)&out[(size_t)r1 * 128 + c] = make_float2(x2, x3);
    }
}

// ---------------------------------------------------------------------------
extern "C" void kernel_launch(void* const* d_in, const int* in_sizes, int n_in,
                              void* d_out, int out_size)
{
    const float* h   = (const float*)d_in[0];
    const int*   adj = (const int*)  d_in[1];
    const float* Wq  = (const float*)d_in[2];
    const float* Wk  = (const float*)d_in[3];
    const float* Wv  = (const float*)d_in[4];
    float*       out = (float*)d_out;
    (void)in_sizes; (void)n_in; (void)out_size;

    cudaFuncSetAttribute(attn_kernel, cudaFuncAttributeMaxDynamicSharedMemorySize, SMEM_DYN);

    qkv_kernel<<<dim3(NN / 64, 3), 256>>>(h, Wq, Wk, Wv);
    pack_kernel<<<256, 256>>>();
    attn_kernel<<<NN / 128, 256, SMEM_DYN>>>(adj, out);
}

// round 15
// speedup vs baseline: 6.3413x; 1.0149x over previous
#include <cuda_runtime.h>
#include <cuda_fp16.h>
#include <math.h>
#include <stdint.h>

#define NN     16384
#define IN_F   256
#define OUT_F  128
#define ALPHA  0.2f
#define LOG2E  1.4426950408889634f

// ---------------- device-global scratch (no allocation) --------------------
__device__ float g_Q[NN * OUT_F];
__device__ float g_K[NN * OUT_F];
__device__ float g_V[NN * OUT_F];
__device__ __half g_Qh[NN * OUT_F];
__device__ __half g_Ql[NN * OUT_F];
// K fragments: [blk 256][kk 8][j 8][lane 32] uint4 = (bh0,bh1,bl0,bl1)  (8 MB)
__device__ __align__(16) uint4 g_Kp[256 * 2048];
// V fragments PAIRED: [blk 256][kk 4][dtp 8][lane 32] uint4 = frag(dt=2dtp).xy, frag(dt=2dtp+1).xy
__device__ __align__(16) uint4 g_Vp[256 * 1024];

// ---------------- helpers ----------------------------------------------
__device__ __forceinline__ uint32_t smem_u32(const void* p) {
    uint32_t a;
    asm("{ .reg .u64 t; cvta.to.shared.u64 t, %1; cvt.u32.u64 %0, t; }" : "=r"(a) : "l"(p));
    return a;
}
__device__ __forceinline__ float ex2f(float x) {
    float y; asm("ex2.approx.f32 %0, %1;" : "=f"(y) : "f"(x)); return y;
}
__device__ __forceinline__ void cpa16(uint32_t s, const void* g) {
    asm volatile("cp.async.cg.shared.global [%0], [%1], 16;" :: "r"(s), "l"(g));
}
#define CPA_COMMIT() asm volatile("cp.async.commit_group;" ::: "memory")
#define CPA_WAIT1()  asm volatile("cp.async.wait_group 1;" ::: "memory")

// m16n8k16 fp16 mma, fp32 accumulate
#define MMA4(c, a, b0v, b1v) \
    asm volatile("mma.sync.aligned.m16n8k16.row.col.f32.f16.f16.f32 " \
        "{%0,%1,%2,%3},{%4,%5,%6,%7},{%8,%9},{%0,%1,%2,%3};" \
        : "+f"((c)[0]), "+f"((c)[1]), "+f"((c)[2]), "+f"((c)[3]) \
        : "r"((a)[0]), "r"((a)[1]), "r"((a)[2]), "r"((a)[3]), "r"(b0v), "r"(b1v))

__device__ __forceinline__ uint32_t h2u(__half2 h) {
    uint32_t u; asm("mov.b32 %0, %1;" : "=r"(u) : "r"(*(uint32_t*)&h)); return u;
}
__device__ __forceinline__ void split_h(float x, __half& h, __half& l) {
    h = __float2half_rn(x);
    l = __float2half_rn(x - __half2float(h));
}

// ---------------------------------------------------------------------------
// Kernel 1: merged QKV projection.  grid = NN/64 = 256 CTAs, 256 threads.
// h tile [64 x 256] loaded ONCE into swizzled smem; 3 GEMMs reuse it.
// Dynamic smem: hs 64x256 fp32 (swizzled) + ws 64x128 fp32 = 96 KB -> 2 CTAs/SM.
// ---------------------------------------------------------------------------
#define QKV_SMEM ((64 * 256 + 64 * 128) * 4)

__global__ __launch_bounds__(256) void qkv_kernel(
    const float* __restrict__ h, const float* __restrict__ Wq,
    const float* __restrict__ Wk, const float* __restrict__ Wv)
{
    extern __shared__ float qsm[];
    float* hsf = qsm;                   // [64][256] with XOR swizzle
    float* wsf = qsm + 64 * 256;        // [64][128] plain

    const int tid = threadIdx.x, ri = tid >> 4, ci = tid & 15;
    const int row0 = blockIdx.x * 64;

    // load h tile once: 4096 float4, 16 per thread; swizzle cols by row/4
#pragma unroll
    for (int l = 0; l < 16; l++) {
        int idx = tid + l * 256;
        int r = idx >> 6, c4 = (idx & 63) * 4;
        int sc = c4 ^ (((r >> 2) & 7) << 2);
        *(float4*)&hsf[r * 256 + sc] = *(const float4*)&h[(size_t)(row0 + r) * IN_F + c4];
    }

    const float* Ws[3]  = {Wq, Wk, Wv};
    float*       Out[3] = {g_Q, g_K, g_V};
    const int swz = (ri & 7) << 2;      // thread's 4 rows share (row>>2)&7 == ri&7

    for (int w = 0; w < 3; w++) {
        const float* W = Ws[w];
        float acc[4][8];
#pragma unroll
        for (int a = 0; a < 4; a++)
#pragma unroll
            for (int b = 0; b < 8; b++) acc[a][b] = 0.f;

        for (int kc = 0; kc < IN_F; kc += 64) {
            __syncthreads();            // prior use of ws (and hs fill) complete
#pragma unroll
            for (int l = 0; l < 8; l++) {
                int idx = tid + l * 256, r = idx >> 5, c4 = (idx & 31) * 4;
                *(float4*)&wsf[r * 128 + c4] = *(const float4*)&W[(size_t)(kc + r) * OUT_F + c4];
            }
            __syncthreads();

#pragma unroll 4
            for (int k = 0; k < 64; k += 4) {
                float a_[4][4];
#pragma unroll
                for (int r = 0; r < 4; r++)
                    *(float4*)a_[r] = *(const float4*)&hsf[(ri * 4 + r) * 256 + ((kc + k) ^ swz)];
#pragma unroll
                for (int kq = 0; kq < 4; kq++) {
                    float4 b0 = *(const float4*)&wsf[(k + kq) * 128 + ci * 8];
                    float4 b1 = *(const float4*)&wsf[(k + kq) * 128 + ci * 8 + 4];
                    float bb[8] = {b0.x, b0.y, b0.z, b0.w, b1.x, b1.y, b1.z, b1.w};
#pragma unroll
                    for (int j = 0; j < 8; j++) {
                        acc[0][j] = fmaf(a_[0][kq], bb[j], acc[0][j]);
                        acc[1][j] = fmaf(a_[1][kq], bb[j], acc[1][j]);
                        acc[2][j] = fmaf(a_[2][kq], bb[j], acc[2][j]);
                        acc[3][j] = fmaf(a_[3][kq], bb[j], acc[3][j]);
                    }
                }
            }
        }
#pragma unroll
        for (int a = 0; a < 4; a++) {
            int r = row0 + ri * 4 + a;
            float4 v0 = {acc[a][0], acc[a][1], acc[a][2], acc[a][3]};
            float4 v1 = {acc[a][4], acc[a][5], acc[a][6], acc[a][7]};
            *(float4*)&Out[w][(size_t)r * OUT_F + ci * 8]     = v0;
            *(float4*)&Out[w][(size_t)r * OUT_F + ci * 8 + 4] = v1;
        }
    }
}

// ---------------------------------------------------------------------------
// Kernel 2: pack Q (fp16 hi/lo rows), K (hi/lo B-fragments), V (paired B-frags)
// ---------------------------------------------------------------------------
__global__ __launch_bounds__(256) void pack_kernel() {
    const int b = blockIdx.x, tid = threadIdx.x;

    for (int idx = tid; idx < 64 * 128; idx += 256) {
        int r = b * 64 + (idx >> 7), c = idx & 127;
        float x = g_Q[(size_t)r * 128 + c];
        __half h, l; split_h(x, h, l);
        g_Qh[(size_t)r * 128 + c] = h;
        g_Ql[(size_t)r * 128 + c] = l;
    }
    // K fragments: thread holds K[n=8j+g][k=16kk+2t+{0,1}] (x) and k+8 (y); lo in z,w
    for (int idx = tid; idx < 2048; idx += 256) {
        int kk = idx >> 8, j = (idx >> 5) & 7, lane = idx & 31;
        int g = lane >> 2, t = lane & 3;
        int n = b * 64 + 8 * j + g;
        int d = 16 * kk + 2 * t;
        const float* kr = &g_K[(size_t)n * 128];
        __half h0, l0, h1, l1, h2, l2, h3, l3;
        split_h(kr[d],     h0, l0); split_h(kr[d + 1], h1, l1);
        split_h(kr[d + 8], h2, l2); split_h(kr[d + 9], h3, l3);
        uint4 u;
        u.x = h2u(__halves2half2(h0, h1));
        u.y = h2u(__halves2half2(h2, h3));
        u.z = h2u(__halves2half2(l0, l1));
        u.w = h2u(__halves2half2(l2, l3));
        g_Kp[(size_t)b * 2048 + idx] = u;
    }
    // V fragments paired: (x,y) = frag for dt=2dtp (dim=16dtp+g), (z,w) = dt=2dtp+1 (dim+8)
    for (int idx = tid; idx < 1024; idx += 256) {
        int kk = idx >> 8, dtp = (idx >> 5) & 7, lane = idx & 31;
        int g = lane >> 2, t = lane & 3;
        int k0 = b * 64 + 16 * kk + 2 * t;
        int dim0 = 16 * dtp + g, dim1 = dim0 + 8;
        uint4 u;
        u.x = h2u(__halves2half2(__float2half_rn(g_V[(size_t)k0 * 128 + dim0]),
                                 __float2half_rn(g_V[(size_t)(k0 + 1) * 128 + dim0])));
        u.y = h2u(__halves2half2(__float2half_rn(g_V[(size_t)(k0 + 8) * 128 + dim0]),
                                 __float2half_rn(g_V[(size_t)(k0 + 9) * 128 + dim0])));
        u.z = h2u(__halves2half2(__float2half_rn(g_V[(size_t)k0 * 128 + dim1]),
                                 __float2half_rn(g_V[(size_t)(k0 + 1) * 128 + dim1])));
        u.w = h2u(__halves2half2(__float2half_rn(g_V[(size_t)(k0 + 8) * 128 + dim1]),
                                 __float2half_rn(g_V[(size_t)(k0 + 9) * 128 + dim1])));
        g_Vp[(size_t)b * 1024 + idx] = u;
    }
}

// ---------------------------------------------------------------------------
// Kernel 3: flash attention via mma.sync.  128 CTAs x 256 thr (8 warps x 16 rows).
// ---------------------------------------------------------------------------
#define SMEM_KV   49152                 // Kp 32KB + Vp 16KB
#define ADJ_ROWB  272                   // 64 ints padded to 68 (bank spread)
#define SMEM_ADJ  (128 * ADJ_ROWB)      // 34816
#define SMEM_DYN  (2 * SMEM_KV + 2 * SMEM_ADJ)

__device__ __forceinline__ void prefetch_tiles(uint32_t smb, int buf, int blk,
                                               const int* adj, int qrow0, int tid)
{
    uint32_t dk = smb + (uint32_t)buf * SMEM_KV;
    const unsigned char* srcK = (const unsigned char*)g_Kp + (size_t)blk * 32768;
    const unsigned char* srcV = (const unsigned char*)g_Vp + (size_t)blk * 16384;
#pragma unroll
    for (int i = 0; i < 8; i++) { int o = (tid + i * 256) * 16; cpa16(dk + o, srcK + o); }
#pragma unroll
    for (int i = 0; i < 4; i++) { int o = (tid + i * 256) * 16; cpa16(dk + 32768 + o, srcV + o); }
    uint32_t da = smb + 2 * SMEM_KV + (uint32_t)buf * SMEM_ADJ;
#pragma unroll
    for (int i = 0; i < 8; i++) {
        int c = tid + i * 256;                 // 2048 x 16B chunks
        int row = c >> 4, c16 = c & 15;
        const int* src = adj + (size_t)(qrow0 + row) * NN + blk * 64 + c16 * 4;
        cpa16(da + row * ADJ_ROWB + c16 * 16, src);
    }
}

__global__ __launch_bounds__(256, 1) void attn_kernel(
    const int* __restrict__ adj, float* __restrict__ out)
{
    extern __shared__ __align__(16) unsigned char smraw[];
    const int tid = threadIdx.x, w = tid >> 5, lane = tid & 31;
    const int g = lane >> 2, t = lane & 3;
    const int qrow0 = blockIdx.x * 128;
    const int r0 = qrow0 + w * 16 + g, r1 = r0 + 8;
    const uint32_t smb = smem_u32(smraw);

    prefetch_tiles(smb, 0, 0, adj, qrow0, tid); CPA_COMMIT();
    prefetch_tiles(smb, 1, 1, adj, qrow0, tid); CPA_COMMIT();

    // Q fragments (held in registers for the whole kernel)
    uint32_t qh[8][4], ql[8][4];
#pragma unroll
    for (int kk = 0; kk < 8; kk++) {
        int c = kk * 16 + 2 * t;
        qh[kk][0] = *(const uint32_t*)&g_Qh[(size_t)r0 * 128 + c];
        qh[kk][1] = *(const uint32_t*)&g_Qh[(size_t)r1 * 128 + c];
        qh[kk][2] = *(const uint32_t*)&g_Qh[(size_t)r0 * 128 + c + 8];
        qh[kk][3] = *(const uint32_t*)&g_Qh[(size_t)r1 * 128 + c + 8];
        ql[kk][0] = *(const uint32_t*)&g_Ql[(size_t)r0 * 128 + c];
        ql[kk][1] = *(const uint32_t*)&g_Ql[(size_t)r1 * 128 + c];
        ql[kk][2] = *(const uint32_t*)&g_Ql[(size_t)r0 * 128 + c + 8];
        ql[kk][3] = *(const uint32_t*)&g_Ql[(size_t)r1 * 128 + c + 8];
    }

    float o[16][4];
#pragma unroll
    for (int dt = 0; dt < 16; dt++)
#pragma unroll
        for (int i = 0; i < 4; i++) o[dt][i] = 0.f;
    float m0 = -1e30f, m1 = -1e30f, l0 = 0.f, l1 = 0.f;

    const int arow0 = (w * 16 + g) * (ADJ_ROWB / 8);       // int2 units
    const int arow1 = (w * 16 + g + 8) * (ADJ_ROWB / 8);

    for (int it = 0; it < 256; ++it) {
        CPA_WAIT1();
        __syncthreads();
        const int buf = it & 1;
        const uint4* khl  = (const uint4*)(smraw + buf * SMEM_KV);
        const uint4* vbf4 = (const uint4*)(smraw + buf * SMEM_KV + 32768);
        const int2*  am   = (const int2*)(smraw + 2 * SMEM_KV + buf * SMEM_ADJ);

        // ---- S = Q K^T (3-term fp16 split, Kh frag reused) ----
        float s[8][4];
#pragma unroll
        for (int j = 0; j < 8; j++)
#pragma unroll
            for (int i = 0; i < 4; i++) s[j][i] = 0.f;
#pragma unroll
        for (int kk = 0; kk < 8; kk++) {
#pragma unroll
            for (int j = 0; j < 8; j++) {
                uint4 b = khl[(((kk << 3) + j) << 5) + lane];
                MMA4(s[j], qh[kk], b.x, b.y);
                MMA4(s[j], ql[kk], b.x, b.y);
                MMA4(s[j], qh[kk], b.z, b.w);
            }
        }

        // ---- leaky relu + adjacency mask + block max ----
        float bm0 = -3e38f, bm1 = -3e38f;
#pragma unroll
        for (int j = 0; j < 8; j++) {
            int2 a0 = am[arow0 + 4 * j + t];
            int2 a1 = am[arow1 + 4 * j + t];
            float v;
            v = s[j][0]; v = fmaxf(v, ALPHA * v); s[j][0] = a0.x ? v : -3e38f;
            v = s[j][1]; v = fmaxf(v, ALPHA * v); s[j][1] = a0.y ? v : -3e38f;
            v = s[j][2]; v = fmaxf(v, ALPHA * v); s[j][2] = a1.x ? v : -3e38f;
            v = s[j][3]; v = fmaxf(v, ALPHA * v); s[j][3] = a1.y ? v : -3e38f;
            bm0 = fmaxf(bm0, fmaxf(s[j][0], s[j][1]));
            bm1 = fmaxf(bm1, fmaxf(s[j][2], s[j][3]));
        }
        bm0 = fmaxf(bm0, __shfl_xor_sync(0xffffffffu, bm0, 1));
        bm0 = fmaxf(bm0, __shfl_xor_sync(0xffffffffu, bm0, 2));
        bm1 = fmaxf(bm1, __shfl_xor_sync(0xffffffffu, bm1, 1));
        bm1 = fmaxf(bm1, __shfl_xor_sync(0xffffffffu, bm1, 2));

        // ---- online-max update with warp-vote skip (ex2(0)==1 exactly) ----
        bool upd = (bm0 > m0) || (bm1 > m1);
        if (__any_sync(0xffffffffu, upd)) {
            float nm0 = fmaxf(m0, bm0), nm1 = fmaxf(m1, bm1);
            float fs0 = ex2f((m0 - nm0) * LOG2E);
            float fs1 = ex2f((m1 - nm1) * LOG2E);
            m0 = nm0; m1 = nm1;
            l0 *= fs0; l1 *= fs1;
#pragma unroll
            for (int dt = 0; dt < 16; dt++) {
                o[dt][0] *= fs0; o[dt][1] *= fs0;
                o[dt][2] *= fs1; o[dt][3] *= fs1;
            }
        }
        const float n0s = m0 * LOG2E, n1s = m1 * LOG2E;

        // ---- exp + convert to fp16 PV A-fragments (register-to-register) ----
        uint32_t pf[4][4];
        float ps0 = 0.f, ps1 = 0.f;
#pragma unroll
        for (int kk = 0; kk < 4; kk++) {
#pragma unroll
            for (int half = 0; half < 2; half++) {
                int j = 2 * kk + half;
                float p0 = ex2f(fmaf(s[j][0], LOG2E, -n0s));
                float p1 = ex2f(fmaf(s[j][1], LOG2E, -n0s));
                float p2 = ex2f(fmaf(s[j][2], LOG2E, -n1s));
                float p3 = ex2f(fmaf(s[j][3], LOG2E, -n1s));
                __half2 hA = __floats2half2_rn(p0, p1);
                __half2 hB = __floats2half2_rn(p2, p3);
                pf[kk][0 + 2 * half] = h2u(hA);
                pf[kk][1 + 2 * half] = h2u(hB);
                float2 fA = __half22float2(hA), fB = __half22float2(hB);
                ps0 += fA.x + fA.y;
                ps1 += fB.x + fB.y;
            }
        }
        l0 += ps0;
        l1 += ps1;

        // ---- O += P V (paired V frags: 2 MMAs per LDS.128) ----
#pragma unroll
        for (int kk = 0; kk < 4; kk++) {
#pragma unroll
            for (int dtp = 0; dtp < 8; dtp++) {
                uint4 v = vbf4[(((kk << 3) + dtp) << 5) + lane];
                MMA4(o[2 * dtp],     pf[kk], v.x, v.y);
                MMA4(o[2 * dtp + 1], pf[kk], v.z, v.w);
            }
        }

        __syncthreads();
        if (it + 2 < 256)
            prefetch_tiles(smb, buf, it + 2, adj, qrow0, tid);
        CPA_COMMIT();
    }

    // ---- epilogue: reduce l across quad, normalize, ELU, store ----
    l0 += __shfl_xor_sync(0xffffffffu, l0, 1);
    l0 += __shfl_xor_sync(0xffffffffu, l0, 2);
    l1 += __shfl_xor_sync(0xffffffffu, l1, 1);
    l1 += __shfl_xor_sync(0xffffffffu, l1, 2);
    const float i0 = 1.f / l0, i1 = 1.f / l1;
#pragma unroll
    for (int dt = 0; dt < 16; dt++) {
        float x0 = o[dt][0] * i0, x1 = o[dt][1] * i0;
        float x2 = o[dt][2] * i1, x3 = o[dt][3] * i1;
        x0 = (x0 > 0.f) ? x0 : (__expf(x0) - 1.f);
        x1 = (x1 > 0.f) ? x1 : (__expf(x1) - 1.f);
        x2 = (x2 > 0.f) ? x2 : (__expf(x2) - 1.f);
        x3 = (x3 > 0.f) ? x3 : (__expf(x3) - 1.f);
        int c = 8 * dt + 2 * t;
        *(float2*)&out[(size_t)r0 * 128 + c] = make_float2(x0, x1);
        *(float2*)&out[(size_t)r1 * 128 + c] = make_float2(x2, x3);
    }
}

// ---------------------------------------------------------------------------
extern "C" void kernel_launch(void* const* d_in, const int* in_sizes, int n_in,
                              void* d_out, int out_size)
{
    const float* h   = (const float*)d_in[0];
    const int*   adj = (const int*)  d_in[1];
    const float* Wq  = (const float*)d_in[2];
    const float* Wk  = (const float*)d_in[3];
    const float* Wv  = (const float*)d_in[4];
    float*       out = (float*)d_out;
    (void)in_sizes; (void)n_in; (void)out_size;

    cudaFuncSetAttribute(qkv_kernel,  cudaFuncAttributeMaxDynamicSharedMemorySize, QKV_SMEM);
    cudaFuncSetAttribute(attn_kernel, cudaFuncAttributeMaxDynamicSharedMemorySize, SMEM_DYN);

    qkv_kernel<<<NN / 64, 256, QKV_SMEM>>>(h, Wq, Wk, Wv);
    pack_kernel<<<256, 256>>>();
    attn_kernel<<<NN / 128, 256, SMEM_DYN>>>(adj, out);
}